// round 1
// baseline (speedup 1.0000x reference)
#include <cuda_runtime.h>

// Problem constants (fixed shapes)
#define NTOK      65536        // B*N = 8*8192
#define CDIM      128
#define TPB       64           // tokens per MLP block
#define XS_STRIDE 132          // padded row stride (floats), 16B-aligned, breaks bank conflicts
#define XS_STRIDE4 33

// Output layout: angles | unnorm | pos | all_to_global (flattened, return order)
#define OUT_ANG 0
#define OUT_UN  (NTOK*14)            // 917504
#define OUT_POS (2*NTOK*14)          // 1835008
#define OUT_ATG (2*NTOK*14 + NTOK*42) // 4587520

// ---------------------------------------------------------------------------
// Kernel A: fused torsion MLP
// smem: Ws[128*128] | Xs[64*132] | Hs[64*132] | Un[64*14]
// ---------------------------------------------------------------------------

__device__ __forceinline__ void load_weight(float* __restrict__ Ws,
                                            const float* __restrict__ W, int tid) {
    const float4* src = (const float4*)W;
    float4* dst = (float4*)Ws;
#pragma unroll
    for (int i = 0; i < 16; i++) dst[tid + i * 256] = src[tid + i * 256];
}

__device__ __forceinline__ void stage_input_relu(float* __restrict__ Xs,
                                                 const float* __restrict__ g,
                                                 int tokBase, int tid) {
    const float4* src = (const float4*)g;
#pragma unroll
    for (int it = 0; it < 8; it++) {
        int i = tid + it * 256;          // 0..2047
        int t = i >> 5;                  // 0..63
        int cq = i & 31;                 // float4 column
        float4 v = src[(tokBase + t) * 32 + cq];
        v.x = fmaxf(v.x, 0.f); v.y = fmaxf(v.y, 0.f);
        v.z = fmaxf(v.z, 0.f); v.w = fmaxf(v.w, 0.f);
        ((float4*)(Xs + t * XS_STRIDE))[cq] = v;
    }
}

template <bool RELU>
__device__ __forceinline__ void gemm_accum(const float* __restrict__ Ws,
                                           const float* __restrict__ Xs,
                                           float acc[4][8], int c0, int t0) {
    const float4* X4 = (const float4*)Xs;
#pragma unroll 2
    for (int kk = 0; kk < 32; kk++) {
        float4 w0 = *(const float4*)(Ws + (kk * 4 + 0) * CDIM + c0);
        float4 w1 = *(const float4*)(Ws + (kk * 4 + 1) * CDIM + c0);
        float4 w2 = *(const float4*)(Ws + (kk * 4 + 2) * CDIM + c0);
        float4 w3 = *(const float4*)(Ws + (kk * 4 + 3) * CDIM + c0);
#pragma unroll
        for (int j = 0; j < 8; j++) {
            float4 x = X4[(t0 + j) * XS_STRIDE4 + kk];
            if (RELU) {
                x.x = fmaxf(x.x, 0.f); x.y = fmaxf(x.y, 0.f);
                x.z = fmaxf(x.z, 0.f); x.w = fmaxf(x.w, 0.f);
            }
            acc[0][j] += x.x * w0.x; acc[1][j] += x.x * w0.y;
            acc[2][j] += x.x * w0.z; acc[3][j] += x.x * w0.w;
            acc[0][j] += x.y * w1.x; acc[1][j] += x.y * w1.y;
            acc[2][j] += x.y * w1.z; acc[3][j] += x.y * w1.w;
            acc[0][j] += x.z * w2.x; acc[1][j] += x.z * w2.y;
            acc[2][j] += x.z * w2.z; acc[3][j] += x.z * w2.w;
            acc[0][j] += x.w * w3.x; acc[1][j] += x.w * w3.y;
            acc[2][j] += x.w * w3.z; acc[3][j] += x.w * w3.w;
        }
    }
}

__device__ __forceinline__ void init_acc(float acc[4][8], const float* b, int c0) {
#pragma unroll
    for (int ci = 0; ci < 4; ci++) {
        float v = b[c0 + ci];
#pragma unroll
        for (int j = 0; j < 8; j++) acc[ci][j] = v;
    }
}

__device__ __forceinline__ void init_acc2(float acc[4][8], const float* ba,
                                          const float* bb, int c0) {
#pragma unroll
    for (int ci = 0; ci < 4; ci++) {
        float v = ba[c0 + ci] + bb[c0 + ci];
#pragma unroll
        for (int j = 0; j < 8; j++) acc[ci][j] = v;
    }
}

template <bool RELU>
__device__ __forceinline__ void store_acc(float* __restrict__ dst,
                                          float acc[4][8], int c0, int t0) {
#pragma unroll
    for (int j = 0; j < 8; j++) {
        float4 v = make_float4(acc[0][j], acc[1][j], acc[2][j], acc[3][j]);
        if (RELU) {
            v.x = fmaxf(v.x, 0.f); v.y = fmaxf(v.y, 0.f);
            v.z = fmaxf(v.z, 0.f); v.w = fmaxf(v.w, 0.f);
        }
        *(float4*)(dst + (t0 + j) * XS_STRIDE + c0) = v;
    }
}

__device__ __forceinline__ void add_acc(float* __restrict__ dst,
                                        float acc[4][8], int c0, int t0) {
#pragma unroll
    for (int j = 0; j < 8; j++) {
        float4* p = (float4*)(dst + (t0 + j) * XS_STRIDE + c0);
        float4 v = *p;
        v.x += acc[0][j]; v.y += acc[1][j]; v.z += acc[2][j]; v.w += acc[3][j];
        *p = v;
    }
}

__global__ void __launch_bounds__(256, 1) mlp_kernel(
    const float* __restrict__ act, const float* __restrict__ init_act,
    const float* __restrict__ Wa, const float* __restrict__ ba,
    const float* __restrict__ Wi, const float* __restrict__ bi,
    const float* __restrict__ w1, const float* __restrict__ b1,
    const float* __restrict__ w2, const float* __restrict__ b2,
    const float* __restrict__ ow, const float* __restrict__ ob,
    float* __restrict__ out)
{
    extern __shared__ float sm[];
    float* Ws = sm;                       // 16384 floats
    float* Xs = sm + 16384;               // 64*132 = 8448
    float* Hs = Xs + 64 * XS_STRIDE;      // 8448
    float* Un = Hs + 64 * XS_STRIDE;      // 896

    const int tid = threadIdx.x;
    const int tokBase = blockIdx.x * TPB;
    const int c0 = (tid & 31) * 4;
    const int t0 = (tid >> 5) * 8;

    float acc[4][8];

    // --- layer 1: x = relu(act)@Wa + ba + relu(init)@Wi + bi ---
    stage_input_relu(Xs, act, tokBase, tid);
    load_weight(Ws, Wa, tid);
    __syncthreads();
    init_acc2(acc, ba, bi, c0);
    gemm_accum<false>(Ws, Xs, acc, c0, t0);
    __syncthreads();
    stage_input_relu(Xs, init_act, tokBase, tid);
    load_weight(Ws, Wi, tid);
    __syncthreads();
    gemm_accum<false>(Ws, Xs, acc, c0, t0);
    __syncthreads();
    store_acc<false>(Xs, acc, c0, t0);   // Xs = x (pre-relu)
    __syncthreads();

    // --- resnet blocks ---
#pragma unroll 1
    for (int blk = 0; blk < 2; blk++) {
        load_weight(Ws, w1 + blk * 16384, tid);
        __syncthreads();
        init_acc(acc, b1 + blk * 128, c0);
        gemm_accum<true>(Ws, Xs, acc, c0, t0);   // relu(x) @ w1
        __syncthreads();
        store_acc<true>(Hs, acc, c0, t0);        // h = relu(.)
        load_weight(Ws, w2 + blk * 16384, tid);
        __syncthreads();
        init_acc(acc, b2 + blk * 128, c0);
        gemm_accum<false>(Ws, Hs, acc, c0, t0);  // h @ w2
        __syncthreads();
        add_acc(Xs, acc, c0, t0);                // x += delta
        __syncthreads();
    }

    // --- output head: unnorm = relu(x) @ ow + ob, 14 channels ---
    for (int i = tid; i < 1792; i += 256) Ws[i] = ow[i];
    __syncthreads();
    {
        int t = tid & 63;
        int hh = tid >> 6;           // 0..3
        int ch0 = hh * 4;
        int cnt = (hh == 3) ? 2 : 4;
        float a0 = 0.f, a1 = 0.f, a2 = 0.f, a3 = 0.f;
#pragma unroll 4
        for (int k = 0; k < 128; k++) {
            float xv = fmaxf(Xs[t * XS_STRIDE + k], 0.f);
            a0 += xv * Ws[k * 14 + ch0 + 0];
            a1 += xv * Ws[k * 14 + ch0 + 1];
            a2 += xv * Ws[k * 14 + ch0 + 2];  // smem OOB-into-Ws for hh==3, unused
            a3 += xv * Ws[k * 14 + ch0 + 3];
        }
        Un[t * 14 + ch0 + 0] = a0 + ob[ch0 + 0];
        Un[t * 14 + ch0 + 1] = a1 + ob[ch0 + 1];
        if (cnt == 4) {
            Un[t * 14 + ch0 + 2] = a2 + ob[ch0 + 2];
            Un[t * 14 + ch0 + 3] = a3 + ob[ch0 + 3];
        }
    }
    __syncthreads();

    // --- normalize + write angles/unnorm ---
    for (int i = tid; i < 448; i += 256) {
        int t = i & 63;
        int a = i >> 6;   // 0..6
        float sv = Un[t * 14 + 2 * a];
        float cv = Un[t * 14 + 2 * a + 1];
        float inv = rsqrtf(sv * sv + cv * cv + 1e-12f);
        int tok = tokBase + t;
        out[OUT_UN + tok * 14 + 2 * a]     = sv;
        out[OUT_UN + tok * 14 + 2 * a + 1] = cv;
        out[OUT_ANG + tok * 14 + 2 * a]     = sv * inv;
        out[OUT_ANG + tok * 14 + 2 * a + 1] = cv * inv;
    }
}

// ---------------------------------------------------------------------------
// Kernel B: torsion_angles_to_frames + atom14 positions
// 32 tokens x 8 groups per block
// ---------------------------------------------------------------------------

__device__ __forceinline__ void compose34(float* __restrict__ o,
                                          const float* __restrict__ A,
                                          const float* __restrict__ Bm) {
#pragma unroll
    for (int r = 0; r < 3; r++) {
        float a0 = A[r * 4 + 0], a1 = A[r * 4 + 1], a2 = A[r * 4 + 2], a3 = A[r * 4 + 3];
#pragma unroll
        for (int c = 0; c < 3; c++)
            o[r * 4 + c] = a0 * Bm[c] + a1 * Bm[4 + c] + a2 * Bm[8 + c];
        o[r * 4 + 3] = a0 * Bm[3] + a1 * Bm[7] + a2 * Bm[11] + a3;
    }
}

__global__ void __launch_bounds__(256) frames_kernel(
    const int* __restrict__ seq, const float* __restrict__ backb,
    const float* __restrict__ dframes, const int* __restrict__ gidx,
    const float* __restrict__ amask, const float* __restrict__ lit,
    float* __restrict__ out)
{
    __shared__ float saf[32][8][12];
    const int tid = threadIdx.x;
    const int g = tid & 7;
    const int tl = tid >> 3;             // 0..31
    const int tok = blockIdx.x * 32 + tl;
    const int s = seq[tok];

    float sv, cv;
    if (g == 0) { sv = 0.f; cv = 1.f; }
    else {
        sv = out[OUT_ANG + tok * 14 + (g - 1) * 2];
        cv = out[OUT_ANG + tok * 14 + (g - 1) * 2 + 1];
    }

    // all_frames[g] = default_frames[s][g] @ rotX(angle)
    const float* df = dframes + (size_t)(s * 8 + g) * 16;
    float F[12];
#pragma unroll
    for (int r = 0; r < 3; r++) {
        float m0 = df[r * 4 + 0], m1 = df[r * 4 + 1], m2 = df[r * 4 + 2], m3 = df[r * 4 + 3];
        F[r * 4 + 0] = m0;
        F[r * 4 + 1] = cv * m1 + sv * m2;
        F[r * 4 + 2] = cv * m2 - sv * m1;
        F[r * 4 + 3] = m3;
    }
#pragma unroll
    for (int i = 0; i < 12; i++) saf[tl][g][i] = F[i];
    __syncthreads();

    // chi chain: slots 5,6,7 become af4@af5, (.)@af6, (.)@af7
    if (g == 0) {
        float A[12], Bm[12], Cm[12];
#pragma unroll
        for (int i = 0; i < 12; i++) A[i] = saf[tl][4][i];
#pragma unroll
        for (int i = 0; i < 12; i++) Bm[i] = saf[tl][5][i];
        compose34(Cm, A, Bm);
#pragma unroll
        for (int i = 0; i < 12; i++) saf[tl][5][i] = Cm[i];
#pragma unroll
        for (int i = 0; i < 12; i++) Bm[i] = saf[tl][6][i];
        compose34(A, Cm, Bm);
#pragma unroll
        for (int i = 0; i < 12; i++) saf[tl][6][i] = A[i];
#pragma unroll
        for (int i = 0; i < 12; i++) Bm[i] = saf[tl][7][i];
        compose34(Cm, A, Bm);
#pragma unroll
        for (int i = 0; i < 12; i++) saf[tl][7][i] = Cm[i];
    }
    __syncthreads();

    // all_to_global[g] = backb @ all_to_bb[g]
    {
        const float* bk = backb + (size_t)tok * 16;
        float Bk[12], L[12], G[12];
#pragma unroll
        for (int i = 0; i < 12; i++) Bk[i] = bk[i];
#pragma unroll
        for (int i = 0; i < 12; i++) L[i] = saf[tl][g][i];
        compose34(G, Bk, L);
        float* o = out + OUT_ATG + (size_t)tok * 128 + g * 16;
        ((float4*)o)[0] = make_float4(G[0], G[1], G[2], G[3]);
        ((float4*)o)[1] = make_float4(G[4], G[5], G[6], G[7]);
        ((float4*)o)[2] = make_float4(G[8], G[9], G[10], G[11]);
        ((float4*)o)[3] = make_float4(0.f, 0.f, 0.f, 1.f);
#pragma unroll
        for (int i = 0; i < 12; i++) saf[tl][g][i] = G[i];
    }
    __syncthreads();

    // atoms: 32 tokens * 14 atoms
    for (int i = tid; i < 448; i += 256) {
        int t2 = i / 14;
        int a = i % 14;
        int tok2 = blockIdx.x * 32 + t2;
        int s2 = seq[tok2];
        int idx = s2 * 14 + a;
        int gg = gidx[idx];
        float m = amask[idx];
        float lx = lit[idx * 3 + 0], ly = lit[idx * 3 + 1], lz = lit[idx * 3 + 2];
        const float* Fp = saf[t2][gg];
        float px = (Fp[0] * lx + Fp[1] * ly + Fp[2]  * lz + Fp[3])  * m;
        float py = (Fp[4] * lx + Fp[5] * ly + Fp[6]  * lz + Fp[7])  * m;
        float pz = (Fp[8] * lx + Fp[9] * ly + Fp[10] * lz + Fp[11]) * m;
        float* po = out + OUT_POS + (size_t)tok2 * 42 + a * 3;
        po[0] = px; po[1] = py; po[2] = pz;
    }
}

// ---------------------------------------------------------------------------

extern "C" void kernel_launch(void* const* d_in, const int* in_sizes, int n_in,
                              void* d_out, int out_size) {
    const int*   seq      = (const int*)  d_in[0];
    const float* backb    = (const float*)d_in[1];
    const float* act      = (const float*)d_in[2];
    const float* init_act = (const float*)d_in[3];
    const float* Wa       = (const float*)d_in[4];
    const float* ba       = (const float*)d_in[5];
    const float* Wi       = (const float*)d_in[6];
    const float* bi       = (const float*)d_in[7];
    const float* w1       = (const float*)d_in[8];
    const float* b1       = (const float*)d_in[9];
    const float* w2       = (const float*)d_in[10];
    const float* b2       = (const float*)d_in[11];
    const float* ow       = (const float*)d_in[12];
    const float* ob       = (const float*)d_in[13];
    const float* dframes  = (const float*)d_in[14];
    const int*   gidx     = (const int*)  d_in[15];
    const float* amask    = (const float*)d_in[16];
    const float* lit      = (const float*)d_in[17];
    float* out = (float*)d_out;

    const int smem = (16384 + 2 * 64 * XS_STRIDE + 64 * 14) * 4;  // 136704
    cudaFuncSetAttribute(mlp_kernel, cudaFuncAttributeMaxDynamicSharedMemorySize, smem);

    mlp_kernel<<<NTOK / TPB, 256, smem>>>(act, init_act, Wa, ba, Wi, bi,
                                          w1, b1, w2, b2, ow, ob, out);
    frames_kernel<<<NTOK / 32, 256>>>(seq, backb, dframes, gidx, amask, lit, out);
}

// round 2
// speedup vs baseline: 1.1986x; 1.1986x over previous
#include <cuda_runtime.h>

// Problem constants (fixed shapes)
#define NTOK      65536        // B*N = 8*8192
#define CDIM      128
#define TPB       64           // tokens per MLP block
#define XT_STRIDE 68           // transposed activation row stride (floats)

// Output layout: angles | unnorm | pos | all_to_global (flattened, return order)
#define OUT_ANG 0
#define OUT_UN  (NTOK*14)             // 917504
#define OUT_POS (2*NTOK*14)           // 1835008
#define OUT_ATG (2*NTOK*14 + NTOK*42) // 4587520

typedef unsigned long long u64;

__device__ __forceinline__ u64 pack2(float a, float b) {
    u64 d; asm("mov.b64 %0,{%1,%2};" : "=l"(d) : "f"(a), "f"(b)); return d;
}
__device__ __forceinline__ float2 unpack2(u64 d) {
    float2 r; asm("mov.b64 {%0,%1},%2;" : "=f"(r.x), "=f"(r.y) : "l"(d)); return r;
}
__device__ __forceinline__ u64 ffma2(u64 a, u64 b, u64 c) {
    u64 d; asm("fma.rn.f32x2 %0,%1,%2,%3;" : "=l"(d) : "l"(a), "l"(b), "l"(c)); return d;
}

// ---------------------------------------------------------------------------
// Kernel A: fused torsion MLP with packed f32x2 FFMA
// smem: Ws[128*128] | Xt[128*68] | Ht[128*68] | Un[64*14]
// Thread tile: warp w, lane l; cq=l&3, tg=l>>2
//   cols  c0 = w*16 + cq*4   (4 cols)
//   toks  t0 = tg*8          (8 tokens = 4 f32x2 pairs)
// ---------------------------------------------------------------------------

__device__ __forceinline__ void load_weight(float* __restrict__ Ws,
                                            const float* __restrict__ W, int tid) {
    const float4* src = (const float4*)W;
    float4* dst = (float4*)Ws;
#pragma unroll
    for (int i = 0; i < 16; i++) dst[tid + i * 256] = src[tid + i * 256];
}

// global [tok][c] --relu--> smem transposed Xt[c][t]
__device__ __forceinline__ void stage_relu_T(float* __restrict__ dst,
                                             const float* __restrict__ g,
                                             int tokBase, int tid) {
    int w = tid >> 5, l = tid & 31;
    int t = w * 8 + (l & 7);
    int cqb = l >> 3;                     // 0..3
    const float4* src = (const float4*)g;
#pragma unroll
    for (int it = 0; it < 8; it++) {
        int cq = cqb + it * 4;            // 0..31
        float4 v = src[(size_t)(tokBase + t) * 32 + cq];
        dst[(4 * cq + 0) * XT_STRIDE + t] = fmaxf(v.x, 0.f);
        dst[(4 * cq + 1) * XT_STRIDE + t] = fmaxf(v.y, 0.f);
        dst[(4 * cq + 2) * XT_STRIDE + t] = fmaxf(v.z, 0.f);
        dst[(4 * cq + 3) * XT_STRIDE + t] = fmaxf(v.w, 0.f);
    }
}

__device__ __forceinline__ void gemm2(const float* __restrict__ Ws,
                                      const float* __restrict__ Xt,
                                      u64 acc2[4][4], int c0, int t0) {
#pragma unroll 2
    for (int kk = 0; kk < 32; kk++) {
#pragma unroll
        for (int r = 0; r < 4; r++) {
            const int k = kk * 4 + r;
            const float4 wv = *(const float4*)(Ws + k * CDIM + c0);
            const u64 wd0 = pack2(wv.x, wv.x);
            const u64 wd1 = pack2(wv.y, wv.y);
            const u64 wd2 = pack2(wv.z, wv.z);
            const u64 wd3 = pack2(wv.w, wv.w);
            const ulonglong2 xa = *(const ulonglong2*)(Xt + k * XT_STRIDE + t0);
            const ulonglong2 xb = *(const ulonglong2*)(Xt + k * XT_STRIDE + t0 + 4);
            u64 xs0 = xa.x, xs1 = xa.y, xs2 = xb.x, xs3 = xb.y;

            acc2[0][0] = ffma2(xs0, wd0, acc2[0][0]);
            acc2[1][0] = ffma2(xs0, wd1, acc2[1][0]);
            acc2[2][0] = ffma2(xs0, wd2, acc2[2][0]);
            acc2[3][0] = ffma2(xs0, wd3, acc2[3][0]);
            acc2[0][1] = ffma2(xs1, wd0, acc2[0][1]);
            acc2[1][1] = ffma2(xs1, wd1, acc2[1][1]);
            acc2[2][1] = ffma2(xs1, wd2, acc2[2][1]);
            acc2[3][1] = ffma2(xs1, wd3, acc2[3][1]);
            acc2[0][2] = ffma2(xs2, wd0, acc2[0][2]);
            acc2[1][2] = ffma2(xs2, wd1, acc2[1][2]);
            acc2[2][2] = ffma2(xs2, wd2, acc2[2][2]);
            acc2[3][2] = ffma2(xs2, wd3, acc2[3][2]);
            acc2[0][3] = ffma2(xs3, wd0, acc2[0][3]);
            acc2[1][3] = ffma2(xs3, wd1, acc2[1][3]);
            acc2[2][3] = ffma2(xs3, wd2, acc2[2][3]);
            acc2[3][3] = ffma2(xs3, wd3, acc2[3][3]);
        }
    }
}

__device__ __forceinline__ void init_acc1(u64 acc2[4][4], const float* b, int c0) {
#pragma unroll
    for (int ci = 0; ci < 4; ci++) {
        u64 bv = pack2(b[c0 + ci], b[c0 + ci]);
#pragma unroll
        for (int jp = 0; jp < 4; jp++) acc2[ci][jp] = bv;
    }
}

__device__ __forceinline__ void init_acc2b(u64 acc2[4][4], const float* ba,
                                           const float* bb, int c0) {
#pragma unroll
    for (int ci = 0; ci < 4; ci++) {
        float v = ba[c0 + ci] + bb[c0 + ci];
        u64 bv = pack2(v, v);
#pragma unroll
        for (int jp = 0; jp < 4; jp++) acc2[ci][jp] = bv;
    }
}

// store relu(acc2) transposed into dst
__device__ __forceinline__ void store_relu_acc(float* __restrict__ dst,
                                               u64 acc2[4][4], int c0, int t0) {
#pragma unroll
    for (int ci = 0; ci < 4; ci++)
#pragma unroll
        for (int jp = 0; jp < 4; jp++) {
            float2 v = unpack2(acc2[ci][jp]);
            v.x = fmaxf(v.x, 0.f); v.y = fmaxf(v.y, 0.f);
            *(float2*)(dst + (c0 + ci) * XT_STRIDE + t0 + 2 * jp) = v;
        }
}

// store relu(xr) transposed into dst
__device__ __forceinline__ void store_relu_xr(float* __restrict__ dst,
                                              float xr[4][8], int c0, int t0) {
#pragma unroll
    for (int ci = 0; ci < 4; ci++)
#pragma unroll
        for (int jp = 0; jp < 4; jp++) {
            float2 v = make_float2(fmaxf(xr[ci][2 * jp], 0.f),
                                   fmaxf(xr[ci][2 * jp + 1], 0.f));
            *(float2*)(dst + (c0 + ci) * XT_STRIDE + t0 + 2 * jp) = v;
        }
}

__global__ void __launch_bounds__(256, 1) mlp_kernel(
    const float* __restrict__ act, const float* __restrict__ init_act,
    const float* __restrict__ Wa, const float* __restrict__ ba,
    const float* __restrict__ Wi, const float* __restrict__ bi,
    const float* __restrict__ w1, const float* __restrict__ b1,
    const float* __restrict__ w2, const float* __restrict__ b2,
    const float* __restrict__ ow, const float* __restrict__ ob,
    float* __restrict__ out)
{
    extern __shared__ float sm[];
    float* Ws = sm;                        // 16384
    float* Xt = sm + 16384;                // 128*68 = 8704
    float* Ht = Xt + 128 * XT_STRIDE;      // 8704
    float* Un = Ht + 128 * XT_STRIDE;      // 896

    const int tid = threadIdx.x;
    const int tokBase = blockIdx.x * TPB;
    const int w = tid >> 5, l = tid & 31;
    const int cq = l & 3, tg = l >> 2;
    const int c0 = w * 16 + cq * 4;
    const int t0 = tg * 8;

    u64 acc2[4][4];
    float xr[4][8];

    // --- layer 1: x = relu(act)@Wa + ba + relu(init)@Wi + bi ---
    stage_relu_T(Xt, act, tokBase, tid);
    load_weight(Ws, Wa, tid);
    __syncthreads();
    init_acc2b(acc2, ba, bi, c0);
    gemm2(Ws, Xt, acc2, c0, t0);
    __syncthreads();
    stage_relu_T(Ht, init_act, tokBase, tid);
    load_weight(Ws, Wi, tid);
    __syncthreads();
    gemm2(Ws, Ht, acc2, c0, t0);
#pragma unroll
    for (int ci = 0; ci < 4; ci++)
#pragma unroll
        for (int jp = 0; jp < 4; jp++) {
            float2 v = unpack2(acc2[ci][jp]);
            xr[ci][2 * jp] = v.x; xr[ci][2 * jp + 1] = v.y;
        }
    // safe: no one reads Xt during gemm over Ht
    store_relu_xr(Xt, xr, c0, t0);
    __syncthreads();

    // --- resnet blocks ---
#pragma unroll 1
    for (int blk = 0; blk < 2; blk++) {
        load_weight(Ws, w1 + blk * 16384, tid);
        __syncthreads();
        init_acc1(acc2, b1 + blk * 128, c0);
        gemm2(Ws, Xt, acc2, c0, t0);                 // relu(x) @ w1
        store_relu_acc(Ht, acc2, c0, t0);            // h = relu(.)
        __syncthreads();
        load_weight(Ws, w2 + blk * 16384, tid);
        __syncthreads();
        init_acc1(acc2, b2 + blk * 128, c0);
        gemm2(Ws, Ht, acc2, c0, t0);                 // h @ w2
#pragma unroll
        for (int ci = 0; ci < 4; ci++)
#pragma unroll
            for (int jp = 0; jp < 4; jp++) {
                float2 v = unpack2(acc2[ci][jp]);
                xr[ci][2 * jp] += v.x; xr[ci][2 * jp + 1] += v.y;
            }
        store_relu_xr(Xt, xr, c0, t0);
        __syncthreads();
    }

    // --- output head: unnorm = relu(x) @ ow + ob, 14 channels ---
    for (int i = tid; i < 1792; i += 256) Ws[i] = ow[i];
    __syncthreads();
    {
        int t = tid & 63;
        int hh = tid >> 6;           // 0..3
        int ch0 = hh * 4;
        float a0 = 0.f, a1 = 0.f, a2 = 0.f, a3 = 0.f;
#pragma unroll 4
        for (int k = 0; k < 128; k++) {
            float xv = Xt[k * XT_STRIDE + t];     // already relu'd
            a0 += xv * Ws[k * 14 + ch0 + 0];
            a1 += xv * Ws[k * 14 + ch0 + 1];
            a2 += xv * Ws[k * 14 + ch0 + 2];  // in-bounds of Ws even for hh==3
            a3 += xv * Ws[k * 14 + ch0 + 3];
        }
        Un[t * 14 + ch0 + 0] = a0 + ob[ch0 + 0];
        Un[t * 14 + ch0 + 1] = a1 + ob[ch0 + 1];
        if (hh != 3) {
            Un[t * 14 + ch0 + 2] = a2 + ob[ch0 + 2];
            Un[t * 14 + ch0 + 3] = a3 + ob[ch0 + 3];
        }
    }
    __syncthreads();

    // --- normalize + write angles/unnorm ---
    for (int i = tid; i < 448; i += 256) {
        int t = i & 63;
        int a = i >> 6;   // 0..6
        float sv = Un[t * 14 + 2 * a];
        float cv = Un[t * 14 + 2 * a + 1];
        float inv = rsqrtf(sv * sv + cv * cv + 1e-12f);
        int tok = tokBase + t;
        out[OUT_UN + tok * 14 + 2 * a]      = sv;
        out[OUT_UN + tok * 14 + 2 * a + 1]  = cv;
        out[OUT_ANG + tok * 14 + 2 * a]     = sv * inv;
        out[OUT_ANG + tok * 14 + 2 * a + 1] = cv * inv;
    }
}

// ---------------------------------------------------------------------------
// Kernel B: torsion_angles_to_frames + atom14 positions
// 32 tokens x 8 groups per block
// ---------------------------------------------------------------------------

__device__ __forceinline__ void compose34(float* __restrict__ o,
                                          const float* __restrict__ A,
                                          const float* __restrict__ Bm) {
#pragma unroll
    for (int r = 0; r < 3; r++) {
        float a0 = A[r * 4 + 0], a1 = A[r * 4 + 1], a2 = A[r * 4 + 2], a3 = A[r * 4 + 3];
#pragma unroll
        for (int c = 0; c < 3; c++)
            o[r * 4 + c] = a0 * Bm[c] + a1 * Bm[4 + c] + a2 * Bm[8 + c];
        o[r * 4 + 3] = a0 * Bm[3] + a1 * Bm[7] + a2 * Bm[11] + a3;
    }
}

__global__ void __launch_bounds__(256) frames_kernel(
    const int* __restrict__ seq, const float* __restrict__ backb,
    const float* __restrict__ dframes, const int* __restrict__ gidx,
    const float* __restrict__ amask, const float* __restrict__ lit,
    float* __restrict__ out)
{
    __shared__ float saf[32][8][12];
    const int tid = threadIdx.x;
    const int g = tid & 7;
    const int tl = tid >> 3;             // 0..31
    const int tok = blockIdx.x * 32 + tl;
    const int s = seq[tok];

    float sv, cv;
    if (g == 0) { sv = 0.f; cv = 1.f; }
    else {
        sv = out[OUT_ANG + tok * 14 + (g - 1) * 2];
        cv = out[OUT_ANG + tok * 14 + (g - 1) * 2 + 1];
    }

    // all_frames[g] = default_frames[s][g] @ rotX(angle)
    const float4* df4 = (const float4*)(dframes + (size_t)(s * 8 + g) * 16);
    float F[12];
#pragma unroll
    for (int r = 0; r < 3; r++) {
        float4 m = df4[r];
        F[r * 4 + 0] = m.x;
        F[r * 4 + 1] = cv * m.y + sv * m.z;
        F[r * 4 + 2] = cv * m.z - sv * m.y;
        F[r * 4 + 3] = m.w;
    }
#pragma unroll
    for (int i = 0; i < 12; i++) saf[tl][g][i] = F[i];
    __syncthreads();

    // chi chain: slots 5,6,7 become af4@af5, (.)@af6, (.)@af7
    if (g == 0) {
        float A[12], Bm[12], Cm[12];
#pragma unroll
        for (int i = 0; i < 12; i++) A[i] = saf[tl][4][i];
#pragma unroll
        for (int i = 0; i < 12; i++) Bm[i] = saf[tl][5][i];
        compose34(Cm, A, Bm);
#pragma unroll
        for (int i = 0; i < 12; i++) saf[tl][5][i] = Cm[i];
#pragma unroll
        for (int i = 0; i < 12; i++) Bm[i] = saf[tl][6][i];
        compose34(A, Cm, Bm);
#pragma unroll
        for (int i = 0; i < 12; i++) saf[tl][6][i] = A[i];
#pragma unroll
        for (int i = 0; i < 12; i++) Bm[i] = saf[tl][7][i];
        compose34(Cm, A, Bm);
#pragma unroll
        for (int i = 0; i < 12; i++) saf[tl][7][i] = Cm[i];
    }
    __syncthreads();

    // all_to_global[g] = backb @ all_to_bb[g]
    {
        const float4* bk4 = (const float4*)(backb + (size_t)tok * 16);
        float Bk[12], L[12], G[12];
        float4 b0 = bk4[0], b1 = bk4[1], b2 = bk4[2];
        Bk[0] = b0.x; Bk[1] = b0.y; Bk[2]  = b0.z; Bk[3]  = b0.w;
        Bk[4] = b1.x; Bk[5] = b1.y; Bk[6]  = b1.z; Bk[7]  = b1.w;
        Bk[8] = b2.x; Bk[9] = b2.y; Bk[10] = b2.z; Bk[11] = b2.w;
#pragma unroll
        for (int i = 0; i < 12; i++) L[i] = saf[tl][g][i];
        compose34(G, Bk, L);
        float* o = out + OUT_ATG + (size_t)tok * 128 + g * 16;
        ((float4*)o)[0] = make_float4(G[0], G[1], G[2], G[3]);
        ((float4*)o)[1] = make_float4(G[4], G[5], G[6], G[7]);
        ((float4*)o)[2] = make_float4(G[8], G[9], G[10], G[11]);
        ((float4*)o)[3] = make_float4(0.f, 0.f, 0.f, 1.f);
#pragma unroll
        for (int i = 0; i < 12; i++) saf[tl][g][i] = G[i];
    }
    __syncthreads();

    // atoms: 32 tokens * 14 atoms
    for (int i = tid; i < 448; i += 256) {
        int t2 = i / 14;
        int a = i % 14;
        int tok2 = blockIdx.x * 32 + t2;
        int s2 = seq[tok2];
        int idx = s2 * 14 + a;
        int gg = gidx[idx];
        float m = amask[idx];
        float lx = lit[idx * 3 + 0], ly = lit[idx * 3 + 1], lz = lit[idx * 3 + 2];
        const float* Fp = saf[t2][gg];
        float px = (Fp[0] * lx + Fp[1] * ly + Fp[2]  * lz + Fp[3])  * m;
        float py = (Fp[4] * lx + Fp[5] * ly + Fp[6]  * lz + Fp[7])  * m;
        float pz = (Fp[8] * lx + Fp[9] * ly + Fp[10] * lz + Fp[11]) * m;
        float* po = out + OUT_POS + (size_t)tok2 * 42 + a * 3;
        po[0] = px; po[1] = py; po[2] = pz;
    }
}

// ---------------------------------------------------------------------------

extern "C" void kernel_launch(void* const* d_in, const int* in_sizes, int n_in,
                              void* d_out, int out_size) {
    const int*   seq      = (const int*)  d_in[0];
    const float* backb    = (const float*)d_in[1];
    const float* act      = (const float*)d_in[2];
    const float* init_act = (const float*)d_in[3];
    const float* Wa       = (const float*)d_in[4];
    const float* ba       = (const float*)d_in[5];
    const float* Wi       = (const float*)d_in[6];
    const float* bi       = (const float*)d_in[7];
    const float* w1       = (const float*)d_in[8];
    const float* b1       = (const float*)d_in[9];
    const float* w2       = (const float*)d_in[10];
    const float* b2       = (const float*)d_in[11];
    const float* ow       = (const float*)d_in[12];
    const float* ob       = (const float*)d_in[13];
    const float* dframes  = (const float*)d_in[14];
    const int*   gidx     = (const int*)  d_in[15];
    const float* amask    = (const float*)d_in[16];
    const float* lit      = (const float*)d_in[17];
    float* out = (float*)d_out;

    const int smem = (16384 + 2 * 128 * XT_STRIDE + 64 * 14) * 4;  // 138752 B
    cudaFuncSetAttribute(mlp_kernel, cudaFuncAttributeMaxDynamicSharedMemorySize, smem);

    mlp_kernel<<<NTOK / TPB, 256, smem>>>(act, init_act, Wa, ba, Wi, bi,
                                          w1, b1, w2, b2, ow, ob, out);
    frames_kernel<<<NTOK / 32, 256>>>(seq, backb, dframes, gidx, amask, lit, out);
}